// round 17
// baseline (speedup 1.0000x reference)
#include <cuda_runtime.h>
#include <cuda_fp16.h>
#include <cstdint>

// ---------------------------------------------------------------------------
// ExtendedGCN: 3-layer GCN (PyG GCNConv) + softmax.
//   Pull-based aggregation over per-call CSR-by-dst, packed (src, norm).
//   Prep = 3 launches: deg (REDG atomics, 2-way) -> scan (49-block, one grid
//   barrier, self-zeroes deg) -> scatter (cursor atomics, 4-way ILP).
//   Layers 1/2 GEMM: native fp16 HMMA (m16n8k16, fp32 accum), fp16 in/out.
//   Layer-3 GEMV (64x16) fused into agg2 epilogue; relu in agg1; softmax agg3.
//   Prep overlapped with layer-1 GEMM on a second stream.
// edge_index is int32 on device (JAX x64 disabled).
// g_deg invariant: zero at call entry (BSS zero-init + scan re-zeroes).
// ---------------------------------------------------------------------------

#define NMAX 50000
#define EMAX 800000
#define SCAN_B 1024
#define NSCANB ((NMAX + SCAN_B - 1) / SCAN_B)   // 49

__device__ __half g_H16[(size_t)NMAX * 128];
__device__ __half g_A16[(size_t)NMAX * 128];
__device__ float  g_H3[(size_t)NMAX * 16];
__device__ float  g_dinv[NMAX];
__device__ int    g_deg[NMAX];
__device__ int    g_offs[NMAX + 1];
__device__ int    g_cursor[NMAX];
__device__ float2 g_csr[EMAX];
__device__ int    g_bsum[NSCANB];

// -------- software grid barrier (sense-reversing; replay-safe state) -------

__device__ volatile unsigned g_bar_gen = 0;
__device__ unsigned g_bar_cnt = 0;

__device__ __forceinline__ void grid_barrier() {
    __syncthreads();
    if (threadIdx.x == 0) {
        __threadfence();
        unsigned my = g_bar_gen;
        if (atomicAdd(&g_bar_cnt, 1) == gridDim.x - 1) {
            atomicExch(&g_bar_cnt, 0);
            __threadfence();
            g_bar_gen = my + 1;
        } else {
            while (g_bar_gen == my) {}
        }
    }
    __syncthreads();
}

// ----------------------------- CSR build ----------------------------------

// 2 edges/thread at stride Q; base lane guarded by t < Q (NOT e < E).
__global__ void deg_kernel(const int* __restrict__ dst, int E, int Q) {
    int t = blockIdx.x * blockDim.x + threadIdx.x;
    if (t >= Q) return;
#pragma unroll
    for (int k = 0; k < 2; k++) {
        int e = t + k * Q;
        if (e < E) atomicAdd(&g_deg[dst[e]], 1);
    }
}

// 49 blocks x 1024: tile scan -> totals -> grid barrier -> prefix; writes
// offs/cursor/dinv; self-zeroes deg.
__global__ void __launch_bounds__(SCAN_B, 1)
scan_kernel(int n, int E) {
    __shared__ int warp_tot[32];
    const int tid = threadIdx.x;
    const int lane = tid & 31;
    const int warp = tid >> 5;
    const int bid = blockIdx.x;
    const int idx = bid * SCAN_B + tid;

    int v = (idx < n) ? g_deg[idx] : 0;
    if (idx < n) {
        g_dinv[idx] = rsqrtf((float)(v + 1));
        g_deg[idx] = 0;
    }

    int inc = v;
#pragma unroll
    for (int o = 1; o < 32; o <<= 1) {
        int x = __shfl_up_sync(0xFFFFFFFFu, inc, o);
        if (lane >= o) inc += x;
    }
    if (lane == 31) warp_tot[warp] = inc;
    __syncthreads();
    if (warp == 0) {
        int w = warp_tot[lane];
        int wi = w;
#pragma unroll
        for (int o = 1; o < 32; o <<= 1) {
            int x = __shfl_up_sync(0xFFFFFFFFu, wi, o);
            if (lane >= o) wi += x;
        }
        warp_tot[lane] = wi - w;
        if (lane == 31) g_bsum[bid] = wi;
    }
    __syncthreads();
    int excl = inc - v + warp_tot[warp];

    grid_barrier();

    int pre = 0;
    for (int j = 0; j < bid; j++) pre += g_bsum[j];
    if (idx < n) {
        int o = excl + pre;
        g_offs[idx] = o;
        g_cursor[idx] = o;
    }
    if (idx == n) g_offs[n] = E;
}

// 4 edges/thread at stride Q: 4 independent atomic->store chains.
// Base lane guarded by t < Q so no edge is visited twice.
__global__ void scatter_kernel(const int* __restrict__ src,
                               const int* __restrict__ dst, int E, int Q) {
    int t = blockIdx.x * blockDim.x + threadIdx.x;
    if (t >= Q) return;
    int e0 = t, e1 = t + Q, e2 = t + 2 * Q, e3 = t + 3 * Q;
    int s0 = 0, s1 = 0, s2 = 0, s3 = 0;
    int p0 = -1, p1 = -1, p2 = -1, p3 = -1;
    float n0 = 0.f, n1 = 0.f, n2 = 0.f, n3 = 0.f;

    {
        s0 = src[e0];
        int d = dst[e0];
        n0 = g_dinv[s0] * g_dinv[d];
        p0 = atomicAdd(&g_cursor[d], 1);
    }
    if (e1 < E) {
        s1 = src[e1];
        int d = dst[e1];
        n1 = g_dinv[s1] * g_dinv[d];
        p1 = atomicAdd(&g_cursor[d], 1);
    }
    if (e2 < E) {
        s2 = src[e2];
        int d = dst[e2];
        n2 = g_dinv[s2] * g_dinv[d];
        p2 = atomicAdd(&g_cursor[d], 1);
    }
    if (e3 < E) {
        s3 = src[e3];
        int d = dst[e3];
        n3 = g_dinv[s3] * g_dinv[d];
        p3 = atomicAdd(&g_cursor[d], 1);
    }
    if (p0 >= 0) g_csr[p0] = make_float2(__int_as_float(s0), n0);
    if (p1 >= 0) g_csr[p1] = make_float2(__int_as_float(s1), n1);
    if (p2 >= 0) g_csr[p2] = make_float2(__int_as_float(s2), n2);
    if (p3 >= 0) g_csr[p3] = make_float2(__int_as_float(s3), n3);
}

// ------------------------- fp16 tensor GEMM --------------------------------

__device__ __forceinline__ void mma_f16(float* c, const uint32_t* a,
                                        uint32_t b0, uint32_t b1) {
    asm volatile(
        "mma.sync.aligned.m16n8k16.row.col.f32.f16.f16.f32 "
        "{%0,%1,%2,%3}, {%4,%5,%6,%7}, {%8,%9}, {%0,%1,%2,%3};\n"
        : "+f"(c[0]), "+f"(c[1]), "+f"(c[2]), "+f"(c[3])
        : "r"(a[0]), "r"(a[1]), "r"(a[2]), "r"(a[3]), "r"(b0), "r"(b1));
}

template <int BN, typename AT>
__global__ void gemm_f16_kernel(const AT* __restrict__ A,
                                const float* __restrict__ W,
                                __half* __restrict__ C, int M, int K, int N) {
    constexpr int BM = 128, BK = 32, THREADS = 256;
    constexpr int AS2 = BK + 8;
    constexpr int WP = BN + 8;
    constexpr int NF = BN / 16;
    constexpr bool A_HALF = (sizeof(AT) == 2);

    __shared__ __align__(16) __half  As[BM * AS2];
    __shared__ __align__(16) __half2 Wp[(BK / 2) * WP];

    const int tid = threadIdx.x;
    const int lane = tid & 31;
    const int warp = tid >> 5;
    const int g = lane >> 2;
    const int tg = lane & 3;
    const int wrb = (warp & 3) * 32;
    const int wcb = (warp >> 2) * (BN / 2);
    const int brow = blockIdx.y * BM;
    const int bcol = blockIdx.x * BN;

    float c[2][NF][4];
#pragma unroll
    for (int mi = 0; mi < 2; mi++)
#pragma unroll
        for (int ni = 0; ni < NF; ni++)
#pragma unroll
            for (int j = 0; j < 4; j++) c[mi][ni][j] = 0.0f;

    for (int k0 = 0; k0 < K; k0 += BK) {
#pragma unroll
        for (int p = tid; p < BM * BK / 4; p += THREADS) {
            int r = p / (BK / 4);
            int c4 = (p % (BK / 4)) * 4;
            int gr = brow + r;
            uint2 pk = make_uint2(0u, 0u);
            if (gr < M) {
                if (A_HALF) {
                    pk = *(const uint2*)&A[(size_t)gr * K + k0 + c4];
                } else {
                    float4 v = *(const float4*)&A[(size_t)gr * K + k0 + c4];
                    __half2 h01 = __floats2half2_rn(v.x, v.y);
                    __half2 h23 = __floats2half2_rn(v.z, v.w);
                    pk.x = *(uint32_t*)&h01;
                    pk.y = *(uint32_t*)&h23;
                }
            }
            *(uint2*)&As[r * AS2 + c4] = pk;
        }
#pragma unroll
        for (int q = tid; q < (BK / 2) * BN; q += THREADS) {
            int kp = q / BN;
            int cc = q % BN;
            float w0 = W[(size_t)(k0 + 2 * kp) * N + bcol + cc];
            float w1 = W[(size_t)(k0 + 2 * kp + 1) * N + bcol + cc];
            Wp[kp * WP + cc] = __floats2half2_rn(w0, w1);
        }
        __syncthreads();

#pragma unroll
        for (int ks = 0; ks < BK / 16; ks++) {
            const int kh = ks * 16;
            const int kp0 = ks * 8;
            uint32_t a[2][4];
#pragma unroll
            for (int mi = 0; mi < 2; mi++) {
                int r0 = wrb + mi * 16 + g;
                a[mi][0] = *(const uint32_t*)&As[r0 * AS2 + kh + 2 * tg];
                a[mi][1] = *(const uint32_t*)&As[(r0 + 8) * AS2 + kh + 2 * tg];
                a[mi][2] = *(const uint32_t*)&As[r0 * AS2 + kh + 2 * tg + 8];
                a[mi][3] = *(const uint32_t*)&As[(r0 + 8) * AS2 + kh + 2 * tg + 8];
            }
#pragma unroll
            for (int ni = 0; ni < NF; ni++) {
                int col = wcb + ni * 8 + g;
                uint32_t b0 = *(const uint32_t*)&Wp[(kp0 + tg) * WP + col];
                uint32_t b1 = *(const uint32_t*)&Wp[(kp0 + tg + 4) * WP + col];
#pragma unroll
                for (int mi = 0; mi < 2; mi++)
                    mma_f16(c[mi][ni], a[mi], b0, b1);
            }
        }
        __syncthreads();
    }

#pragma unroll
    for (int mi = 0; mi < 2; mi++) {
        int gr0 = brow + wrb + mi * 16 + g;
        int gr1 = gr0 + 8;
#pragma unroll
        for (int ni = 0; ni < NF; ni++) {
            int gc = bcol + wcb + ni * 8 + 2 * tg;
            if (gr0 < M)
                *(__half2*)&C[(size_t)gr0 * N + gc] =
                    __floats2half2_rn(c[mi][ni][0], c[mi][ni][1]);
            if (gr1 < M)
                *(__half2*)&C[(size_t)gr1 * N + gc] =
                    __floats2half2_rn(c[mi][ni][2], c[mi][ni][3]);
        }
    }
}

// ---------------- agg1: fp16 gather, relu, fp16 out (D=128) ----------------

__global__ void agg1_kernel(__half* __restrict__ out,
                            const __half* __restrict__ H,
                            const float* __restrict__ b, int n) {
    constexpr int D = 128;
    int warp = (blockIdx.x * blockDim.x + threadIdx.x) >> 5;
    int f = threadIdx.x & 31;
    int i = warp;
    if (i >= n) return;

    float di = g_dinv[i];
    float s2 = di * di;
    uint2 hp = *(const uint2*)&H[(size_t)i * D + 4 * f];
    float2 h01 = __half22float2(*(__half2*)&hp.x);
    float2 h23 = __half22float2(*(__half2*)&hp.y);
    float4 bb = ((const float4*)b)[f];
    float4 acc;
    acc.x = bb.x + s2 * h01.x;
    acc.y = bb.y + s2 * h01.y;
    acc.z = bb.z + s2 * h23.x;
    acc.w = bb.w + s2 * h23.y;

    int beg = g_offs[i], end = g_offs[i + 1];
#pragma unroll 8
    for (int e = beg; e < end; e++) {
        float2 p = __ldg(&g_csr[e]);
        int s = __float_as_int(p.x);
        float nrm = p.y;
        uint2 vp = *(const uint2*)&H[(size_t)s * D + 4 * f];
        float2 v01 = __half22float2(*(__half2*)&vp.x);
        float2 v23 = __half22float2(*(__half2*)&vp.y);
        acc.x += nrm * v01.x;
        acc.y += nrm * v01.y;
        acc.z += nrm * v23.x;
        acc.w += nrm * v23.y;
    }

    acc.x = fmaxf(acc.x, 0.0f);
    acc.y = fmaxf(acc.y, 0.0f);
    acc.z = fmaxf(acc.z, 0.0f);
    acc.w = fmaxf(acc.w, 0.0f);

    uint2 o;
    *(__half2*)&o.x = __floats2half2_rn(acc.x, acc.y);
    *(__half2*)&o.y = __floats2half2_rn(acc.z, acc.w);
    *(uint2*)&out[(size_t)i * D + 4 * f] = o;
}

// ------- agg2 + fused 64x16 GEMV: h2 = agg(H2)+b2; logits = h2 @ W3 --------

__global__ void agg2_gemv_kernel(float* __restrict__ outH3,
                                 const __half* __restrict__ H,
                                 const float* __restrict__ b2,
                                 const float* __restrict__ W3, int n) {
    __shared__ __align__(16) float W3s[64 * 16];
    {
        int t = threadIdx.x;
        if (t < 256) ((float4*)W3s)[t] = ((const float4*)W3)[t];
    }
    __syncthreads();

    constexpr int D = 64, LPN = 16, NPW = 2;
    int warp = (blockIdx.x * blockDim.x + threadIdx.x) >> 5;
    int lane = threadIdx.x & 31;
    int grp = lane >> 4;
    int f = lane & 15;
    int i = warp * NPW + grp;
    if (i >= n) return;

    float di = g_dinv[i];
    float s2 = di * di;
    uint2 hp = *(const uint2*)&H[(size_t)i * D + 4 * f];
    float2 h01 = __half22float2(*(__half2*)&hp.x);
    float2 h23 = __half22float2(*(__half2*)&hp.y);
    float4 bb = ((const float4*)b2)[f];
    float4 acc;
    acc.x = bb.x + s2 * h01.x;
    acc.y = bb.y + s2 * h01.y;
    acc.z = bb.z + s2 * h23.x;
    acc.w = bb.w + s2 * h23.y;

    int beg = g_offs[i], end = g_offs[i + 1];
#pragma unroll 8
    for (int e = beg; e < end; e++) {
        float2 p = __ldg(&g_csr[e]);
        int s = __float_as_int(p.x);
        float nrm = p.y;
        uint2 vp = *(const uint2*)&H[(size_t)s * D + 4 * f];
        float2 v01 = __half22float2(*(__half2*)&vp.x);
        float2 v23 = __half22float2(*(__half2*)&vp.y);
        acc.x += nrm * v01.x;
        acc.y += nrm * v01.y;
        acc.z += nrm * v23.x;
        acc.w += nrm * v23.y;
    }

    float part = 0.0f;
#pragma unroll
    for (int j = 0; j < LPN; j++) {
        float ax = __shfl_sync(0xFFFFFFFFu, acc.x, j, 16);
        float ay = __shfl_sync(0xFFFFFFFFu, acc.y, j, 16);
        float az = __shfl_sync(0xFFFFFFFFu, acc.z, j, 16);
        float aw = __shfl_sync(0xFFFFFFFFu, acc.w, j, 16);
        part += ax * W3s[(4 * j + 0) * 16 + f];
        part += ay * W3s[(4 * j + 1) * 16 + f];
        part += az * W3s[(4 * j + 2) * 16 + f];
        part += aw * W3s[(4 * j + 3) * 16 + f];
    }
    outH3[(size_t)i * 16 + f] = part;
}

// ---------------- agg3: fp32 gather over logits + softmax (D=16) -----------

__global__ void agg3_kernel(float* __restrict__ out,
                            const float* __restrict__ H,
                            const float* __restrict__ b, int n) {
    constexpr int LPN = 4, NPW = 8;
    int warp = (blockIdx.x * blockDim.x + threadIdx.x) >> 5;
    int lane = threadIdx.x & 31;
    int grp = lane / LPN;
    int f = lane % LPN;
    int i = warp * NPW + grp;
    if (i >= n) return;

    float di = g_dinv[i];
    float s2 = di * di;
    float4 h = ((const float4*)H)[(size_t)i * LPN + f];
    float4 bb = ((const float4*)b)[f];
    float4 acc;
    acc.x = bb.x + s2 * h.x;
    acc.y = bb.y + s2 * h.y;
    acc.z = bb.z + s2 * h.z;
    acc.w = bb.w + s2 * h.w;

    int beg = g_offs[i], end = g_offs[i + 1];
#pragma unroll 8
    for (int e = beg; e < end; e++) {
        float2 p = __ldg(&g_csr[e]);
        int s = __float_as_int(p.x);
        float nrm = p.y;
        float4 v = ((const float4*)H)[(size_t)s * LPN + f];
        acc.x += nrm * v.x;
        acc.y += nrm * v.y;
        acc.z += nrm * v.z;
        acc.w += nrm * v.w;
    }

    float m = fmaxf(fmaxf(acc.x, acc.y), fmaxf(acc.z, acc.w));
#pragma unroll
    for (int o = 1; o < LPN; o <<= 1)
        m = fmaxf(m, __shfl_xor_sync(0xFFFFFFFFu, m, o, LPN));
    acc.x = __expf(acc.x - m);
    acc.y = __expf(acc.y - m);
    acc.z = __expf(acc.z - m);
    acc.w = __expf(acc.w - m);
    float s = acc.x + acc.y + acc.z + acc.w;
#pragma unroll
    for (int o = 1; o < LPN; o <<= 1)
        s += __shfl_xor_sync(0xFFFFFFFFu, s, o, LPN);
    float inv = 1.0f / s;
    acc.x *= inv;
    acc.y *= inv;
    acc.z *= inv;
    acc.w *= inv;

    ((float4*)out)[(size_t)i * LPN + f] = acc;
}

// ------------------------------- launch -----------------------------------

static cudaStream_t s_gemm = nullptr;
static cudaEvent_t  s_evFork = nullptr, s_evJoin = nullptr;

extern "C" void kernel_launch(void* const* d_in, const int* in_sizes, int n_in,
                              void* d_out, int out_size) {
    const float* x  = (const float*)d_in[0];
    const int*   ei = (const int*)d_in[1];   // int32 (JAX x64 disabled)
    const float* W1 = (const float*)d_in[2];
    const float* b1 = (const float*)d_in[3];
    const float* W2 = (const float*)d_in[4];
    const float* b2 = (const float*)d_in[5];
    const float* W3 = (const float*)d_in[6];
    const float* b3 = (const float*)d_in[7];

    const int n = in_sizes[0] / 128;
    const int E = in_sizes[1] / 2;
    const int* src = ei;
    const int* dst = ei + E;

    float* H3;
    __half *H16, *A16;
    cudaGetSymbolAddress((void**)&H16, g_H16);
    cudaGetSymbolAddress((void**)&A16, g_A16);
    cudaGetSymbolAddress((void**)&H3, g_H3);

    if (s_gemm == nullptr) {
        cudaStreamCreateWithFlags(&s_gemm, cudaStreamNonBlocking);
        cudaEventCreateWithFlags(&s_evFork, cudaEventDisableTiming);
        cudaEventCreateWithFlags(&s_evJoin, cudaEventDisableTiming);
    }

    const int T = 256;
    auto blocks = [&](long long work) { return (int)((work + T - 1) / T); };
    const int nScanBlocks = (n + SCAN_B - 1) / SCAN_B;
    const int gy = (n + 127) / 128;

    // Fork: layer-1 GEMM (independent of CSR) on side stream.
    cudaEventRecord(s_evFork, 0);
    cudaStreamWaitEvent(s_gemm, s_evFork, 0);
    gemm_f16_kernel<128, float>
        <<<dim3(1, gy), 256, 0, s_gemm>>>(x, W1, H16, n, 128, 128);
    cudaEventRecord(s_evJoin, s_gemm);

    // CSR build on main stream (3 launches; g_deg zero at entry).
    const int Q2 = (E + 1) / 2;
    deg_kernel<<<blocks(Q2), T>>>(dst, E, Q2);
    scan_kernel<<<nScanBlocks, SCAN_B>>>(n, E);
    const int Q4 = (E + 3) / 4;
    scatter_kernel<<<blocks(Q4), T>>>(src, dst, E, Q4);

    // Join: agg1 needs both CSR and H.
    cudaStreamWaitEvent(0, s_evJoin, 0);

    // ----- layer 1 aggregation (fp16 in/out, relu fused) -----
    agg1_kernel<<<blocks((long long)n * 32), T>>>(A16, H16, b1, n);

    // ----- layer 2: 128 -> 64 (fp16 HMMA) -----
    gemm_f16_kernel<64, __half>
        <<<dim3(1, gy), 256>>>(A16, W2, H16, n, 128, 64);

    // ----- layer 2 agg + fused layer-3 GEMV -> logits -----
    agg2_gemv_kernel<<<blocks((long long)n * 16), T>>>(H3, H16, b2, W3, n);

    // ----- layer 3 aggregation + softmax -> d_out -----
    agg3_kernel<<<blocks((long long)n * 4), T>>>((float*)d_out, H3, b3, n);
}